// round 6
// baseline (speedup 1.0000x reference)
#include <cuda_runtime.h>
#include <math.h>

// Problem: input (8, 64, 64, 3) fp32 -> scalar fp32.
#define NB   8
#define NPIX 4096            // 64*64
#define NELE (NB * NPIX)     // 32768
#define PRE_BLKS 64          // blocks in the abs/minmax pass

// ---- scratch (no allocations allowed -> __device__ globals) ----
__device__ __align__(16) float g_a[NELE];   // |x|.sum(-1), layout [b][i]
__device__ float        g_bmin[PRE_BLKS];   // per-block min (all written each run)
__device__ float        g_bmax[PRE_BLKS];
__device__ double       g_part[512];        // per-k_main-block partial sums
__device__ unsigned int g_count = 0;        // completion counter (self-resetting)

// ---- packed f32x2 helpers (Blackwell FFMA2 — only reachable via PTX) ----
__device__ __forceinline__ unsigned long long pk2(float lo, float hi) {
    unsigned long long r;
    asm("mov.b64 %0, {%1,%2};" : "=l"(r) : "f"(lo), "f"(hi));
    return r;
}
__device__ __forceinline__ void unpk2(unsigned long long v, float& lo, float& hi) {
    asm("mov.b64 {%0,%1}, %2;" : "=f"(lo), "=f"(hi) : "l"(v));
}
__device__ __forceinline__ unsigned long long mul2(unsigned long long a, unsigned long long b) {
    unsigned long long r;
    asm("mul.rn.f32x2 %0, %1, %2;" : "=l"(r) : "l"(a), "l"(b));
    return r;
}
__device__ __forceinline__ unsigned long long fma2(unsigned long long a, unsigned long long b,
                                                   unsigned long long c) {
    unsigned long long r;
    asm("fma.rn.f32x2 %0, %1, %2, %3;" : "=l"(r) : "l"(a), "l"(b), "l"(c));
    return r;
}

// ---------------------------------------------------------------
// 4 pixels / thread: 3 x LDG.128 in, 1 x STG.128 out. grid 64 x 128.
__global__ void __launch_bounds__(128) k_pre(const float4* __restrict__ in4) {
    int t = blockIdx.x * 128 + threadIdx.x;            // 0..8191
    float4 a = in4[t * 3 + 0];                          // x0 y0 z0 x1
    float4 b = in4[t * 3 + 1];                          // y1 z1 x2 y2
    float4 c = in4[t * 3 + 2];                          // z2 x3 y3 z3

    float4 s;
    s.x = fabsf(a.x) + fabsf(a.y) + fabsf(a.z);
    s.y = fabsf(a.w) + fabsf(b.x) + fabsf(b.y);
    s.z = fabsf(b.z) + fabsf(b.w) + fabsf(c.x);
    s.w = fabsf(c.y) + fabsf(c.z) + fabsf(c.w);
    *(float4*)&g_a[t * 4] = s;

    float mn = fminf(fminf(s.x, s.y), fminf(s.z, s.w));
    float mx = fmaxf(fmaxf(s.x, s.y), fmaxf(s.z, s.w));
    #pragma unroll
    for (int o = 16; o; o >>= 1) {
        mn = fminf(mn, __shfl_xor_sync(0xffffffffu, mn, o));
        mx = fmaxf(mx, __shfl_xor_sync(0xffffffffu, mx, o));
    }
    __shared__ float smn[4], smx[4];
    int wid = threadIdx.x >> 5, lid = threadIdx.x & 31;
    if (lid == 0) { smn[wid] = mn; smx[wid] = mx; }
    __syncthreads();
    if (threadIdx.x == 0) {
        #pragma unroll
        for (int w = 1; w < 4; w++) { mn = fminf(mn, smn[w]); mx = fmaxf(mx, smx[w]); }
        g_bmin[blockIdx.x] = mn;
        g_bmax[blockIdx.x] = mx;
    }
}

// ---------------------------------------------------------------
// grid (8, 64): block = (i-tile of 512 pixels = 8 rows) x (j-row of 64 pixels).
// Each thread: pixels iA = base+tid and iB = iA+256 (same ix, rows r and r+4).
// Normalization fused into loads; final 512-way reduce done by last block.
__global__ void __launch_bounds__(256) k_main(float* __restrict__ out) {
    __shared__ float  s_m[4];
    __shared__ float  s_dist[512];                     // 8 local i-rows x 64 dx
    __shared__ __align__(16) float s_fj[512];          // j-row f, pixel-major [jx][b]
    __shared__ double s_red[8];
    __shared__ bool   s_last;

    int tid  = threadIdx.x;
    int lane = tid & 31, wid = tid >> 5;

    // ---- reduce the 64 per-block min/max pairs (warps 0-1) ----
    if (tid < 64) {
        float mn = g_bmin[tid], mx = g_bmax[tid];
        #pragma unroll
        for (int o = 16; o; o >>= 1) {
            mn = fminf(mn, __shfl_xor_sync(0xffffffffu, mn, o));
            mx = fmaxf(mx, __shfl_xor_sync(0xffffffffu, mx, o));
        }
        if (lane == 0) { s_m[wid] = mn; s_m[2 + wid] = mx; }
    }
    __syncthreads();
    float mn  = fminf(s_m[0], s_m[1]);
    float mx  = fmaxf(s_m[2], s_m[3]);
    float inv = 1.0f / (mx - mn);
    float nb  = -mn * inv;                              // f = fma(a, inv, nb)

    int jy  = blockIdx.y;
    int ry0 = blockIdx.x * 8;                           // first i row of this block

    // distance rows needed by this block: 512 sqrts
    #pragma unroll
    for (int e = tid; e < 512; e += 256) {
        int r  = e >> 6, dx = e & 63;
        int dy = ry0 + r - jy;
        s_dist[e] = sqrtf((float)(dy * dy + dx * dx));
    }

    // normalized f of the j row, transposed to pixel-major
    int jbase = jy * 64;
    #pragma unroll
    for (int e = tid; e < 512; e += 256) {
        int b = e >> 6, x = e & 63;
        s_fj[x * 8 + b] = fmaf(g_a[b * NPIX + jbase + x], inv, nb);
    }

    // this thread's two pixels, packed as 4 f32x2 each
    int iA = blockIdx.x * 512 + tid;
    int iB = iA + 256;
    unsigned long long fA[4], fB[4];
    #pragma unroll
    for (int h = 0; h < 4; h++) {
        float a0 = fmaf(g_a[(2 * h)     * NPIX + iA], inv, nb);
        float a1 = fmaf(g_a[(2 * h + 1) * NPIX + iA], inv, nb);
        fA[h] = pk2(a0, a1);
        float b0 = fmaf(g_a[(2 * h)     * NPIX + iB], inv, nb);
        float b1 = fmaf(g_a[(2 * h + 1) * NPIX + iB], inv, nb);
        fB[h] = pk2(b0, b1);
    }
    __syncthreads();

    int ix = tid & 63;                                  // same for iA and iB
    const float* drow0 = s_dist + ((tid >> 6) << 6);    // row r
    const float* drow1 = drow0 + 256;                   // row r+4

    unsigned long long acc = 0ull;                      // packed (+0.0f, +0.0f)
    #pragma unroll 8
    for (int jj = 0; jj < 64; jj++) {
        ulonglong2 ja = *(const ulonglong2*)(s_fj + jj * 8);      // b 0..3
        ulonglong2 jb = *(const ulonglong2*)(s_fj + jj * 8 + 4);  // b 4..7
        int m = ix - jj; m = m < 0 ? -m : m;
        float d0 = drow0[m], d1 = drow1[m];

        unsigned long long p = mul2(fA[0], ja.x);       // lanes: even-b / odd-b
        p = fma2(fA[1], ja.y, p);
        p = fma2(fA[2], jb.x, p);
        p = fma2(fA[3], jb.y, p);
        acc = fma2(p, pk2(d0, d0), acc);

        unsigned long long q = mul2(fB[0], ja.x);
        q = fma2(fB[1], ja.y, q);
        q = fma2(fB[2], jb.x, q);
        q = fma2(fB[3], jb.y, q);
        acc = fma2(q, pk2(d1, d1), acc);
    }

    float alo, ahi;
    unpk2(acc, alo, ahi);
    double dacc = (double)alo + (double)ahi;
    #pragma unroll
    for (int o = 16; o; o >>= 1)
        dacc += __shfl_xor_sync(0xffffffffu, dacc, o);
    if (lane == 0) s_red[wid] = dacc;
    __syncthreads();
    if (tid == 0) {
        double s = s_red[0];
        #pragma unroll
        for (int w = 1; w < 8; w++) s += s_red[w];
        g_part[blockIdx.y * 8 + blockIdx.x] = s;
        __threadfence();
        s_last = (atomicAdd(&g_count, 1u) == 511u);
    }
    __syncthreads();

    // ---- last block to finish reduces all 512 partials (fixed order) ----
    if (s_last) {
        double s = ((volatile double*)g_part)[tid]
                 + ((volatile double*)g_part)[tid + 256];
        #pragma unroll
        for (int o = 16; o; o >>= 1)
            s += __shfl_xor_sync(0xffffffffu, s, o);
        if (lane == 0) s_red[wid] = s;
        __syncthreads();
        if (tid == 0) {
            double t = s_red[0];
            #pragma unroll
            for (int w = 1; w < 8; w++) t += s_red[w];
            out[0] = (float)(t / 134217728.0);   // / (B*N*N) = 8*4096*4096
            g_count = 0;                          // reset for next graph replay
        }
    }
}

extern "C" void kernel_launch(void* const* d_in, const int* in_sizes, int n_in,
                              void* d_out, int out_size) {
    const float4* in4 = (const float4*)d_in[0];
    float*        out = (float*)d_out;

    k_pre<<<PRE_BLKS, 128>>>(in4);
    dim3 g(8, 64);
    k_main<<<g, 256>>>(out);
}

// round 7
// speedup vs baseline: 1.1065x; 1.1065x over previous
#include <cuda_runtime.h>
#include <math.h>

// Problem: input (8, 64, 64, 3) fp32 -> scalar fp32.
#define NB   8
#define NPIX 4096            // 64*64
#define NELE (NB * NPIX)     // 32768
#define PRE_BLKS 64          // blocks in the abs/minmax pass
#define MAIN_BLKS 576        // symmetric block set (see c_off)

// ---- scratch (no allocations allowed -> __device__ globals) ----
__device__ __align__(16) float g_a[NELE];   // |x|.sum(-1), layout [b][i]
__device__ float        g_bmin[PRE_BLKS];   // per-block min (all written each run)
__device__ float        g_bmax[PRE_BLKS];
__device__ double       g_part[MAIN_BLKS];  // per-k_main-block partial sums
__device__ unsigned int g_count = 0;        // completion counter (self-resetting)

// cumulative block offsets per i-tile bx: each bx keeps jy in [8*bx, 64),
// 2 half-row chunks per jy -> counts 2*(64-8*bx).
__constant__ int c_off[9] = {0, 128, 240, 336, 416, 480, 528, 560, 576};

// ---- packed f32x2 helpers (Blackwell FFMA2 — only reachable via PTX) ----
__device__ __forceinline__ unsigned long long pk2(float lo, float hi) {
    unsigned long long r;
    asm("mov.b64 %0, {%1,%2};" : "=l"(r) : "f"(lo), "f"(hi));
    return r;
}
__device__ __forceinline__ void unpk2(unsigned long long v, float& lo, float& hi) {
    asm("mov.b64 {%0,%1}, %2;" : "=f"(lo), "=f"(hi) : "l"(v));
}
__device__ __forceinline__ unsigned long long mul2(unsigned long long a, unsigned long long b) {
    unsigned long long r;
    asm("mul.rn.f32x2 %0, %1, %2;" : "=l"(r) : "l"(a), "l"(b));
    return r;
}
__device__ __forceinline__ unsigned long long fma2(unsigned long long a, unsigned long long b,
                                                   unsigned long long c) {
    unsigned long long r;
    asm("fma.rn.f32x2 %0, %1, %2, %3;" : "=l"(r) : "l"(a), "l"(b), "l"(c));
    return r;
}

// ---------------------------------------------------------------
// 4 pixels / thread: 3 x LDG.128 in, 1 x STG.128 out. grid 64 x 128.
__global__ void __launch_bounds__(128) k_pre(const float4* __restrict__ in4) {
    int t = blockIdx.x * 128 + threadIdx.x;            // 0..8191
    float4 a = in4[t * 3 + 0];
    float4 b = in4[t * 3 + 1];
    float4 c = in4[t * 3 + 2];

    float4 s;
    s.x = fabsf(a.x) + fabsf(a.y) + fabsf(a.z);
    s.y = fabsf(a.w) + fabsf(b.x) + fabsf(b.y);
    s.z = fabsf(b.z) + fabsf(b.w) + fabsf(c.x);
    s.w = fabsf(c.y) + fabsf(c.z) + fabsf(c.w);
    *(float4*)&g_a[t * 4] = s;

    float mn = fminf(fminf(s.x, s.y), fminf(s.z, s.w));
    float mx = fmaxf(fmaxf(s.x, s.y), fmaxf(s.z, s.w));
    #pragma unroll
    for (int o = 16; o; o >>= 1) {
        mn = fminf(mn, __shfl_xor_sync(0xffffffffu, mn, o));
        mx = fmaxf(mx, __shfl_xor_sync(0xffffffffu, mx, o));
    }
    __shared__ float smn[4], smx[4];
    int wid = threadIdx.x >> 5, lid = threadIdx.x & 31;
    if (lid == 0) { smn[wid] = mn; smx[wid] = mx; }
    __syncthreads();
    if (threadIdx.x == 0) {
        #pragma unroll
        for (int w = 1; w < 4; w++) { mn = fminf(mn, smn[w]); mx = fmaxf(mx, smx[w]); }
        g_bmin[blockIdx.x] = mn;
        g_bmax[blockIdx.x] = mx;
    }
}

// ---------------------------------------------------------------
// Symmetric main kernel. Block = (i-tile of 8 rows) x (half j-row of 32).
// Only blocks with jy >= first i-row are launched; pair weight {0,1,2} is
// folded into the distance table, so Sum == full Sum_ij D_ij (f_i . f_j).
// Each thread handles pixels iA = tile+tid (row r) and iB = iA+256 (row r+4).
__global__ void __launch_bounds__(256) k_main(float* __restrict__ out) {
    __shared__ float  s_m[4];
    __shared__ __align__(8)  float2 s_d2[256];         // [r 0..3][dx 0..63], w*dist for rows r, r+4
    __shared__ __align__(16) float  s_fj[256];         // 32 j x 8 b, pixel-major
    __shared__ double s_red[8];
    __shared__ bool   s_last;

    int tid  = threadIdx.x;
    int lane = tid & 31, wid = tid >> 5;

    // ---- decode (bx, jy, jlo) from linear block id ----
    int bid = blockIdx.x;
    int bx = 0;
    #pragma unroll
    for (int t = 1; t < 8; t++) bx += (bid >= c_off[t]);
    int rel = bid - c_off[bx];
    int jy  = 8 * bx + (rel >> 1);
    int jlo = (rel & 1) << 5;                          // 0 or 32
    int ry0 = bx * 8;

    // ---- reduce the 64 per-block min/max pairs (warps 0-1) ----
    if (tid < 64) {
        float mn = g_bmin[tid], mx = g_bmax[tid];
        #pragma unroll
        for (int o = 16; o; o >>= 1) {
            mn = fminf(mn, __shfl_xor_sync(0xffffffffu, mn, o));
            mx = fmaxf(mx, __shfl_xor_sync(0xffffffffu, mx, o));
        }
        if (lane == 0) { s_m[wid] = mn; s_m[2 + wid] = mx; }
    }
    __syncthreads();
    float mn  = fminf(s_m[0], s_m[1]);
    float mx  = fmaxf(s_m[2], s_m[3]);
    float inv = 1.0f / (mx - mn);
    float nb  = -mn * inv;                              // f = fma(a, inv, nb)

    // ---- weighted distance table: one entry per thread ----
    {
        int r  = tid >> 6, dx = tid & 63;
        int ry = ry0 + r, ry4 = ry + 4;
        int dy0 = jy - ry, dy1 = jy - ry4;
        float w0 = (jy > ry)  ? 2.0f : (jy == ry  ? 1.0f : 0.0f);
        float w1 = (jy > ry4) ? 2.0f : (jy == ry4 ? 1.0f : 0.0f);
        float2 d;
        d.x = w0 * sqrtf((float)(dy0 * dy0 + dx * dx));
        d.y = w1 * sqrtf((float)(dy1 * dy1 + dx * dx));
        s_d2[tid] = d;
    }

    // ---- normalized f of the 32-j chunk, pixel-major ----
    {
        int b = tid >> 5, x = tid & 31;
        s_fj[x * 8 + b] = fmaf(g_a[b * NPIX + jy * 64 + jlo + x], inv, nb);
    }

    // ---- this thread's two pixels, packed as 4 f32x2 each ----
    int iA = bx * 512 + tid;
    int iB = iA + 256;
    unsigned long long fA[4], fB[4];
    #pragma unroll
    for (int h = 0; h < 4; h++) {
        float a0 = fmaf(g_a[(2 * h)     * NPIX + iA], inv, nb);
        float a1 = fmaf(g_a[(2 * h + 1) * NPIX + iA], inv, nb);
        fA[h] = pk2(a0, a1);
        float b0 = fmaf(g_a[(2 * h)     * NPIX + iB], inv, nb);
        float b1 = fmaf(g_a[(2 * h + 1) * NPIX + iB], inv, nb);
        fB[h] = pk2(b0, b1);
    }
    __syncthreads();

    int ix = tid & 63;
    const float2* drow = s_d2 + ((tid >> 6) << 6);

    unsigned long long acc = 0ull;                      // packed (+0.0f, +0.0f)
    #pragma unroll 8
    for (int jj = 0; jj < 32; jj++) {
        ulonglong2 ja = *(const ulonglong2*)(s_fj + jj * 8);      // b 0..3
        ulonglong2 jb = *(const ulonglong2*)(s_fj + jj * 8 + 4);  // b 4..7
        int m = ix - (jlo + jj); m = m < 0 ? -m : m;
        float2 d = drow[m];                              // one LDS.64

        unsigned long long p = mul2(fA[0], ja.x);        // lanes: even-b / odd-b
        p = fma2(fA[1], ja.y, p);
        p = fma2(fA[2], jb.x, p);
        p = fma2(fA[3], jb.y, p);
        acc = fma2(p, pk2(d.x, d.x), acc);

        unsigned long long q = mul2(fB[0], ja.x);
        q = fma2(fB[1], ja.y, q);
        q = fma2(fB[2], jb.x, q);
        q = fma2(fB[3], jb.y, q);
        acc = fma2(q, pk2(d.y, d.y), acc);
    }

    float alo, ahi;
    unpk2(acc, alo, ahi);
    double dacc = (double)alo + (double)ahi;
    #pragma unroll
    for (int o = 16; o; o >>= 1)
        dacc += __shfl_xor_sync(0xffffffffu, dacc, o);
    if (lane == 0) s_red[wid] = dacc;
    __syncthreads();
    if (tid == 0) {
        double s = s_red[0];
        #pragma unroll
        for (int w = 1; w < 8; w++) s += s_red[w];
        g_part[bid] = s;
        __threadfence();
        s_last = (atomicAdd(&g_count, 1u) == (MAIN_BLKS - 1u));
    }
    __syncthreads();

    // ---- last block to finish reduces all partials (fixed order) ----
    if (s_last) {
        double s = 0.0;
        for (int k = tid; k < MAIN_BLKS; k += 256)
            s += ((volatile double*)g_part)[k];
        #pragma unroll
        for (int o = 16; o; o >>= 1)
            s += __shfl_xor_sync(0xffffffffu, s, o);
        if (lane == 0) s_red[wid] = s;
        __syncthreads();
        if (tid == 0) {
            double t = s_red[0];
            #pragma unroll
            for (int w = 1; w < 8; w++) t += s_red[w];
            out[0] = (float)(t / 134217728.0);   // / (B*N*N) = 8*4096*4096
            g_count = 0;                          // reset for next graph replay
        }
    }
}

extern "C" void kernel_launch(void* const* d_in, const int* in_sizes, int n_in,
                              void* d_out, int out_size) {
    const float4* in4 = (const float4*)d_in[0];
    float*        out = (float*)d_out;

    k_pre<<<PRE_BLKS, 128>>>(in4);
    k_main<<<MAIN_BLKS, 256>>>(out);
}